// round 4
// baseline (speedup 1.0000x reference)
#include <cuda_runtime.h>

#define NVEH 4096
#define NT 256
#define PAST 25
#define LEADLEN (NT + PAST - 1)   // 280
#define WARPS_PER_CTA 28
#define NCTA ((NVEH + WARPS_PER_CTA - 1) / WARPS_PER_CTA)   // 147
#define NTHREADS (WARPS_PER_CTA * 32)                        // 896

typedef unsigned long long ull;

// ---- shared memory layout (float offsets) ----
#define W1_OFF   0                 // 288   : conv1_w [3][3][32]
#define B1_OFF   288               // 32
#define B2P_OFF  320               // 64    : float2 {b2[c], b2[c+32]}
#define W2P_OFF  384               // 6144  : float2 {w2[kc][c], w2[kc][c+32]}, idx kc*32+c, kc=k*32+ci
#define WD2P_OFF 6528              // 3840  : float2 {W[i][2q], W[i][2q+1]}, idx q*384+i
#define BD2_OFF  10368             // 10
#define WD1_OFF  10378             // 10
#define BD1_OFF  10388             // 1 (+3 pad)
#define XBUF_OFF 10392             // 28 warps * 27 pos * 4 floats (zero-padded borders)
#define P1_OFF   13416             // 28 * 13 * 32 * 2 floats (duplicated-pair)
#define SMEM_FLOATS (P1_OFF + WARPS_PER_CTA * 13 * 32 * 2)   // 36712 -> 146848 B

__device__ __forceinline__ ull ffma2(ull a, ull b, ull c) {
    ull d;
    asm("fma.rn.f32x2 %0, %1, %2, %3;" : "=l"(d) : "l"(a), "l"(b), "l"(c));
    return d;
}
__device__ __forceinline__ void unpk(ull v, float& lo, float& hi) {
    asm("mov.b64 {%0, %1}, %2;" : "=f"(lo), "=f"(hi) : "l"(v));
}
__device__ __forceinline__ ull pkdup(float x) {
    ull d;
    asm("mov.b64 %0, {%1, %1};" : "=l"(d) : "f"(x));
    return d;
}

__global__ void __launch_bounds__(NTHREADS, 1)
rnncf_kernel(const float* __restrict__ lead, const float* __restrict__ cur,
             const float* __restrict__ w1g, const float* __restrict__ b1g,
             const float* __restrict__ w2g, const float* __restrict__ b2g,
             const float* __restrict__ wd2g, const float* __restrict__ bd2g,
             const float* __restrict__ wd1g, const float* __restrict__ bd1g,
             float* __restrict__ out)
{
    extern __shared__ float sm[];
    const int tid = threadIdx.x;

    // ---------- cooperative weight staging ----------
    for (int i = tid; i < 288; i += NTHREADS) sm[W1_OFF + i] = w1g[i];
    for (int i = tid; i < 32;  i += NTHREADS) sm[B1_OFF + i] = b1g[i];
    {
        float2* b2p = (float2*)(sm + B2P_OFF);
        for (int i = tid; i < 32; i += NTHREADS)
            b2p[i] = make_float2(b2g[i], b2g[i + 32]);
        float2* w2p = (float2*)(sm + W2P_OFF);
        for (int i = tid; i < 3072; i += NTHREADS) {
            int kc = i >> 5, c = i & 31;
            w2p[i] = make_float2(w2g[kc * 64 + c], w2g[kc * 64 + c + 32]);
        }
        float2* wd2p = (float2*)(sm + WD2P_OFF);
        for (int i = tid; i < 1920; i += NTHREADS) {
            int q = i / 384, r = i - q * 384;
            wd2p[i] = make_float2(wd2g[r * 10 + 2 * q], wd2g[r * 10 + 2 * q + 1]);
        }
    }
    for (int i = tid; i < 10; i += NTHREADS) sm[BD2_OFF + i] = bd2g[i];
    for (int i = tid; i < 10; i += NTHREADS) sm[WD1_OFF + i] = wd1g[i];
    if (tid == 0) sm[BD1_OFF] = bd1g[0];
    // zero xbuf: border slots (0 and 26) must stay 0; per-step writes touch 1..25 only
    for (int i = tid; i < WARPS_PER_CTA * 27 * 4; i += NTHREADS) sm[XBUF_OFF + i] = 0.0f;
    __syncthreads();

    const int wid = tid >> 5, lane = tid & 31;
    const int v = blockIdx.x * WARPS_PER_CTA + wid;
    if (v >= NVEH) return;

    float* xb = sm + XBUF_OFF + wid * (27 * 4);
    ull* p1u = (ull*)(sm + P1_OFF) + wid * (13 * 32);
    const ull* w2u = (const ull*)(sm + W2P_OFF);
    const ull* wdu = (const ull*)(sm + WD2P_OFF);
    const float2* lead2 = (const float2*)lead + (size_t)v * LEADLEN;
    const float2* cur2  = (const float2*)cur  + (size_t)v * PAST;
    float2* out2 = (float2*)out + (size_t)v * NT;

    // ---------- initial window: lane i (<25) holds CNN input column i ----------
    float x0 = 0.f, x1 = 0.f, x2 = 0.f, tp = 0.f, ts = 0.f;
    if (lane < PAST) {
        float2 cs = cur2[lane];
        float2 ld = lead2[lane];
        x0 = (ld.x - cs.x) * (1.0f / 200.0f);
        x1 = cs.y * (1.0f / 40.0f);
        x2 = ld.y * (1.0f / 40.0f);
        tp = cs.x; ts = cs.y;
    }
    float p24 = __shfl_sync(0xffffffffu, tp, 24);
    float s24 = __shfl_sync(0xffffffffu, ts, 24);

    #pragma unroll 1
    for (int t = 0; t < NT; ++t) {
        // prefetch next lead pair (hides GMEM latency behind this step's CNN)
        float2 ldn = make_float2(0.f, 0.f);
        if (lane == 24 && t < NT - 1) ldn = lead2[t + PAST];

        // publish window to smem (index i+1; 0 and 26 remain zero pad)
        if (lane < PAST)
            *(float4*)(xb + (lane + 1) * 4) = make_float4(x0, x1, x2, 0.0f);
        __syncwarp();

        // ---------- conv1 (lane = out channel) + relu + pool1, streaming ----------
        float w1r[9];
        #pragma unroll
        for (int i = 0; i < 9; ++i) w1r[i] = sm[W1_OFF + i * 32 + lane];
        float b1r = sm[B1_OFF + lane];

        float4 a = *(float4*)(xb);
        float4 b = *(float4*)(xb + 4);
        #pragma unroll
        for (int m = 0; m < 12; ++m) {
            float4 c1 = *(float4*)(xb + (2 * m + 2) * 4);
            float4 c2 = *(float4*)(xb + (2 * m + 3) * 4);
            float h0 = b1r;
            h0 = fmaf(a.x,  w1r[0], h0); h0 = fmaf(a.y,  w1r[1], h0); h0 = fmaf(a.z,  w1r[2], h0);
            h0 = fmaf(b.x,  w1r[3], h0); h0 = fmaf(b.y,  w1r[4], h0); h0 = fmaf(b.z,  w1r[5], h0);
            h0 = fmaf(c1.x, w1r[6], h0); h0 = fmaf(c1.y, w1r[7], h0); h0 = fmaf(c1.z, w1r[8], h0);
            float h1 = b1r;
            h1 = fmaf(b.x,  w1r[0], h1); h1 = fmaf(b.y,  w1r[1], h1); h1 = fmaf(b.z,  w1r[2], h1);
            h1 = fmaf(c1.x, w1r[3], h1); h1 = fmaf(c1.y, w1r[4], h1); h1 = fmaf(c1.z, w1r[5], h1);
            h1 = fmaf(c2.x, w1r[6], h1); h1 = fmaf(c2.y, w1r[7], h1); h1 = fmaf(c2.z, w1r[8], h1);
            float p = fmaxf(fmaxf(h0, 0.0f), fmaxf(h1, 0.0f));
            p1u[m * 32 + lane] = pkdup(p);   // duplicated {p,p} for packed conv2
            a = c1; b = c2;
        }
        {   // pool slot 12: conv position 24 alone (SAME pool pad on the right)
            float4 c1 = *(float4*)(xb + 26 * 4);   // zero pad column
            float h0 = b1r;
            h0 = fmaf(a.x,  w1r[0], h0); h0 = fmaf(a.y,  w1r[1], h0); h0 = fmaf(a.z,  w1r[2], h0);
            h0 = fmaf(b.x,  w1r[3], h0); h0 = fmaf(b.y,  w1r[4], h0); h0 = fmaf(b.z,  w1r[5], h0);
            h0 = fmaf(c1.x, w1r[6], h0); h0 = fmaf(c1.y, w1r[7], h0); h0 = fmaf(c1.z, w1r[8], h0);
            p1u[12 * 32 + lane] = pkdup(fmaxf(h0, 0.0f));
        }
        __syncwarp();

        // ---------- conv2 (lane -> out channels {lane, lane+32}), packed f32x2 ----------
        // Split into two position chunks to cap live registers at 72/thread.
        const ull b2pair = ((const ull*)(sm + B2P_OFF))[lane];
        float fa[6], fb[6];

        {   // chunk A: output positions 0..5 -> pool slots 0..2
            ull acc[6];
            #pragma unroll
            for (int j = 0; j < 6; ++j) acc[j] = b2pair;
            #pragma unroll 1
            for (int ci = 0; ci < 32; ++ci) {
                const ull* pp = p1u + ci;               // broadcast reads
                ull w0  = w2u[(ci     ) * 32 + lane];   // k=0
                ull w1v = w2u[(ci + 32) * 32 + lane];   // k=1
                ull w2v = w2u[(ci + 64) * 32 + lane];   // k=2
                ull q0 = pp[0],   q1 = pp[32],  q2 = pp[64],  q3 = pp[96];
                ull q4 = pp[128], q5 = pp[160], q6 = pp[192], q7 = pp[224];
                acc[0] = ffma2(q2, w2v, ffma2(q1, w1v, ffma2(q0, w0, acc[0])));
                acc[1] = ffma2(q3, w2v, ffma2(q2, w1v, ffma2(q1, w0, acc[1])));
                acc[2] = ffma2(q4, w2v, ffma2(q3, w1v, ffma2(q2, w0, acc[2])));
                acc[3] = ffma2(q5, w2v, ffma2(q4, w1v, ffma2(q3, w0, acc[3])));
                acc[4] = ffma2(q6, w2v, ffma2(q5, w1v, ffma2(q4, w0, acc[4])));
                acc[5] = ffma2(q7, w2v, ffma2(q6, w1v, ffma2(q5, w0, acc[5])));
            }
            #pragma unroll
            for (int jj = 0; jj < 3; ++jj) {
                float l0, h0c, l1, h1c;
                unpk(acc[2 * jj],     l0, h0c);
                unpk(acc[2 * jj + 1], l1, h1c);
                fa[jj] = fmaxf(fmaxf(l0, 0.f), fmaxf(l1, 0.f));
                fb[jj] = fmaxf(fmaxf(h0c, 0.f), fmaxf(h1c, 0.f));
            }
        }
        {   // chunk B: output positions 6..10 -> pool slots 3..5
            ull acc[5];
            #pragma unroll
            for (int j = 0; j < 5; ++j) acc[j] = b2pair;
            #pragma unroll 1
            for (int ci = 0; ci < 32; ++ci) {
                const ull* pp = p1u + ci;
                ull w0  = w2u[(ci     ) * 32 + lane];
                ull w1v = w2u[(ci + 32) * 32 + lane];
                ull w2v = w2u[(ci + 64) * 32 + lane];
                ull q6 = pp[192], q7 = pp[224], q8 = pp[256], q9 = pp[288];
                ull q10 = pp[320], q11 = pp[352], q12 = pp[384];
                acc[0] = ffma2(q8,  w2v, ffma2(q7,  w1v, ffma2(q6,  w0, acc[0])));
                acc[1] = ffma2(q9,  w2v, ffma2(q8,  w1v, ffma2(q7,  w0, acc[1])));
                acc[2] = ffma2(q10, w2v, ffma2(q9,  w1v, ffma2(q8,  w0, acc[2])));
                acc[3] = ffma2(q11, w2v, ffma2(q10, w1v, ffma2(q9,  w0, acc[3])));
                acc[4] = ffma2(q12, w2v, ffma2(q11, w1v, ffma2(q10, w0, acc[4])));
            }
            #pragma unroll
            for (int jj = 0; jj < 2; ++jj) {
                float l0, h0c, l1, h1c;
                unpk(acc[2 * jj],     l0, h0c);
                unpk(acc[2 * jj + 1], l1, h1c);
                fa[3 + jj] = fmaxf(fmaxf(l0, 0.f), fmaxf(l1, 0.f));
                fb[3 + jj] = fmaxf(fmaxf(h0c, 0.f), fmaxf(h1c, 0.f));
            }
            float l0, h0c;
            unpk(acc[4], l0, h0c);    // position 10, window of one
            fa[5] = fmaxf(l0, 0.f);
            fb[5] = fmaxf(h0c, 0.f);
        }

        // ---------- dense2 (packed over output pairs) + warp reduce + dense1 ----------
        ull fap[6], fbp[6];
        #pragma unroll
        for (int jj = 0; jj < 6; ++jj) { fap[jj] = pkdup(fa[jj]); fbp[jj] = pkdup(fb[jj]); }

        float d[10];
        #pragma unroll
        for (int q = 0; q < 5; ++q) {
            ull s = 0ull;   // packed {0.f, 0.f}
            const ull* wq = wdu + q * 384 + lane;
            #pragma unroll
            for (int jj = 0; jj < 6; ++jj) {
                s = ffma2(fap[jj], wq[jj * 64],      s);   // flat i = jj*64 + lane
                s = ffma2(fbp[jj], wq[jj * 64 + 32], s);   // flat i = jj*64 + 32 + lane
            }
            unpk(s, d[2 * q], d[2 * q + 1]);
        }
        #pragma unroll
        for (int off = 16; off > 0; off >>= 1) {
            #pragma unroll
            for (int o = 0; o < 10; ++o)
                d[o] += __shfl_xor_sync(0xffffffffu, d[o], off);
        }
        float y = sm[BD1_OFF];
        #pragma unroll
        for (int o = 0; o < 10; ++o)
            y = fmaf(fmaxf(d[o] + sm[BD2_OFF + o], 0.0f), sm[WD1_OFF + o], y);
        float accv = fmaf(10.0f, y, -6.0f);   // (MAXA-MINA)*y + MINA

        // ---------- recurrence + output ----------
        float pp2 = fmaf(0.1f, s24,  p24);
        float ps2 = fmaf(0.1f, accv, s24);
        if (lane == 0) out2[t] = make_float2(pp2, ps2);

        x0 = __shfl_down_sync(0xffffffffu, x0, 1);
        x1 = __shfl_down_sync(0xffffffffu, x1, 1);
        x2 = __shfl_down_sync(0xffffffffu, x2, 1);
        if (lane == 24) {
            x0 = (ldn.x - pp2) * (1.0f / 200.0f);
            x1 = ps2 * (1.0f / 40.0f);
            x2 = ldn.y * (1.0f / 40.0f);
        }
        p24 = pp2; s24 = ps2;
    }
}

extern "C" void kernel_launch(void* const* d_in, const int* in_sizes, int n_in,
                              void* d_out, int out_size)
{
    const float* lead = (const float*)d_in[0];   // (4096, 280, 2)
    const float* cur  = (const float*)d_in[1];   // (4096, 25, 2)
    // d_in[2] = mask (unused by the reference computation)
    const float* w1  = (const float*)d_in[3];
    const float* b1  = (const float*)d_in[4];
    const float* w2  = (const float*)d_in[5];
    const float* b2  = (const float*)d_in[6];
    const float* wd2 = (const float*)d_in[7];
    const float* bd2 = (const float*)d_in[8];
    const float* wd1 = (const float*)d_in[9];
    const float* bd1 = (const float*)d_in[10];
    float* out = (float*)d_out;                   // (4096, 256, 2)

    (void)in_sizes; (void)n_in; (void)out_size;

    size_t smem_bytes = (size_t)SMEM_FLOATS * sizeof(float);
    cudaFuncSetAttribute(rnncf_kernel,
                         cudaFuncAttributeMaxDynamicSharedMemorySize,
                         (int)smem_bytes);
    rnncf_kernel<<<NCTA, NTHREADS, smem_bytes>>>(
        lead, cur, w1, b1, w2, b2, wd2, bd2, wd1, bd1, out);
}

// round 5
// speedup vs baseline: 1.0010x; 1.0010x over previous
#include <cuda_runtime.h>

#define NVEH 4096
#define NT 256
#define PAST 25
#define LEADLEN (NT + PAST - 1)   // 280
#define WARPS_PER_CTA 28
#define NCTA ((NVEH + WARPS_PER_CTA - 1) / WARPS_PER_CTA)   // 147
#define NTHREADS (WARPS_PER_CTA * 32)                        // 896

typedef unsigned long long ull;

// ---- shared memory layout (float offsets) ----
#define W1_OFF   0                 // 288   : conv1_w [3][3][32]
#define B1_OFF   288               // 32
#define B2P_OFF  320               // 64    : float2 {b2[c], b2[c+32]}
#define W2P_OFF  384               // 6144  : float2 {w2[kc][c], w2[kc][c+32]}, idx kc*32+c, kc=k*32+ci
#define WD2P_OFF 6528              // 3840  : float2 {W[i][2q], W[i][2q+1]}, idx q*384+i
#define BD2_OFF  10368             // 10
#define WD1_OFF  10378             // 10
#define BD1_OFF  10388             // 1 (+3 pad)
#define XBUF_OFF 10392             // 28 warps * 27 pos * 4 floats (zero-padded borders)
#define P1_OFF   13416             // 28 * 13 * 32 * 2 floats (duplicated-pair)
#define SMEM_FLOATS (P1_OFF + WARPS_PER_CTA * 13 * 32 * 2)   // 36712 -> 146848 B

__device__ __forceinline__ ull ffma2(ull a, ull b, ull c) {
    ull d;
    asm("fma.rn.f32x2 %0, %1, %2, %3;" : "=l"(d) : "l"(a), "l"(b), "l"(c));
    return d;
}
__device__ __forceinline__ void unpk(ull v, float& lo, float& hi) {
    asm("mov.b64 {%0, %1}, %2;" : "=f"(lo), "=f"(hi) : "l"(v));
}
__device__ __forceinline__ ull pkdup(float x) {
    ull d;
    asm("mov.b64 %0, {%1, %1};" : "=l"(d) : "f"(x));
    return d;
}

__global__ void __launch_bounds__(NTHREADS, 1)
rnncf_kernel(const float* __restrict__ lead, const float* __restrict__ cur,
             const float* __restrict__ w1g, const float* __restrict__ b1g,
             const float* __restrict__ w2g, const float* __restrict__ b2g,
             const float* __restrict__ wd2g, const float* __restrict__ bd2g,
             const float* __restrict__ wd1g, const float* __restrict__ bd1g,
             float* __restrict__ out)
{
    extern __shared__ float sm[];
    const int tid = threadIdx.x;

    // ---------- cooperative weight staging ----------
    for (int i = tid; i < 288; i += NTHREADS) sm[W1_OFF + i] = w1g[i];
    for (int i = tid; i < 32;  i += NTHREADS) sm[B1_OFF + i] = b1g[i];
    {
        float2* b2p = (float2*)(sm + B2P_OFF);
        for (int i = tid; i < 32; i += NTHREADS)
            b2p[i] = make_float2(b2g[i], b2g[i + 32]);
        float2* w2p = (float2*)(sm + W2P_OFF);
        for (int i = tid; i < 3072; i += NTHREADS) {
            int kc = i >> 5, c = i & 31;
            w2p[i] = make_float2(w2g[kc * 64 + c], w2g[kc * 64 + c + 32]);
        }
        float2* wd2p = (float2*)(sm + WD2P_OFF);
        for (int i = tid; i < 1920; i += NTHREADS) {
            int q = i / 384, r = i - q * 384;
            wd2p[i] = make_float2(wd2g[r * 10 + 2 * q], wd2g[r * 10 + 2 * q + 1]);
        }
    }
    for (int i = tid; i < 10; i += NTHREADS) sm[BD2_OFF + i] = bd2g[i];
    for (int i = tid; i < 10; i += NTHREADS) sm[WD1_OFF + i] = wd1g[i];
    if (tid == 0) sm[BD1_OFF] = bd1g[0];
    // zero xbuf: border slots (0 and 26) must stay 0; per-step writes touch 1..25 only
    for (int i = tid; i < WARPS_PER_CTA * 27 * 4; i += NTHREADS) sm[XBUF_OFF + i] = 0.0f;
    __syncthreads();

    const int wid = tid >> 5, lane = tid & 31;
    const int v = blockIdx.x * WARPS_PER_CTA + wid;
    if (v >= NVEH) return;

    float* xb = sm + XBUF_OFF + wid * (27 * 4);
    ull* p1u = (ull*)(sm + P1_OFF) + wid * (13 * 32);
    const ull* w2u = (const ull*)(sm + W2P_OFF);
    const ull* wdu = (const ull*)(sm + WD2P_OFF);
    const float2* lead2 = (const float2*)lead + (size_t)v * LEADLEN;
    const float2* cur2  = (const float2*)cur  + (size_t)v * PAST;
    float2* out2 = (float2*)out + (size_t)v * NT;

    // ---------- initial window: lane i (<25) holds CNN input column i ----------
    float x0 = 0.f, x1 = 0.f, x2 = 0.f, tp = 0.f, ts = 0.f;
    if (lane < PAST) {
        float2 cs = cur2[lane];
        float2 ld = lead2[lane];
        x0 = (ld.x - cs.x) * (1.0f / 200.0f);
        x1 = cs.y * (1.0f / 40.0f);
        x2 = ld.y * (1.0f / 40.0f);
        tp = cs.x; ts = cs.y;
    }
    float p24 = __shfl_sync(0xffffffffu, tp, 24);
    float s24 = __shfl_sync(0xffffffffu, ts, 24);

    #pragma unroll 1
    for (int t = 0; t < NT; ++t) {
        // prefetch next lead pair (hides GMEM latency behind this step's CNN)
        float2 ldn = make_float2(0.f, 0.f);
        if (lane == 24 && t < NT - 1) ldn = lead2[t + PAST];

        // publish window to smem (index i+1; 0 and 26 remain zero pad)
        if (lane < PAST)
            *(float4*)(xb + (lane + 1) * 4) = make_float4(x0, x1, x2, 0.0f);
        __syncwarp();

        // ---------- conv1 (lane = out channel) + relu + pool1, streaming ----------
        float w1r[9];
        #pragma unroll
        for (int i = 0; i < 9; ++i) w1r[i] = sm[W1_OFF + i * 32 + lane];
        float b1r = sm[B1_OFF + lane];

        float4 a = *(float4*)(xb);
        float4 b = *(float4*)(xb + 4);
        #pragma unroll
        for (int m = 0; m < 12; ++m) {
            float4 c1 = *(float4*)(xb + (2 * m + 2) * 4);
            float4 c2 = *(float4*)(xb + (2 * m + 3) * 4);
            float h0 = b1r;
            h0 = fmaf(a.x,  w1r[0], h0); h0 = fmaf(a.y,  w1r[1], h0); h0 = fmaf(a.z,  w1r[2], h0);
            h0 = fmaf(b.x,  w1r[3], h0); h0 = fmaf(b.y,  w1r[4], h0); h0 = fmaf(b.z,  w1r[5], h0);
            h0 = fmaf(c1.x, w1r[6], h0); h0 = fmaf(c1.y, w1r[7], h0); h0 = fmaf(c1.z, w1r[8], h0);
            float h1 = b1r;
            h1 = fmaf(b.x,  w1r[0], h1); h1 = fmaf(b.y,  w1r[1], h1); h1 = fmaf(b.z,  w1r[2], h1);
            h1 = fmaf(c1.x, w1r[3], h1); h1 = fmaf(c1.y, w1r[4], h1); h1 = fmaf(c1.z, w1r[5], h1);
            h1 = fmaf(c2.x, w1r[6], h1); h1 = fmaf(c2.y, w1r[7], h1); h1 = fmaf(c2.z, w1r[8], h1);
            float p = fmaxf(fmaxf(h0, 0.0f), fmaxf(h1, 0.0f));
            p1u[m * 32 + lane] = pkdup(p);   // duplicated {p,p} for packed conv2
            a = c1; b = c2;
        }
        {   // pool slot 12: conv position 24 alone (SAME pool pad on the right)
            float4 c1 = *(float4*)(xb + 26 * 4);   // zero pad column
            float h0 = b1r;
            h0 = fmaf(a.x,  w1r[0], h0); h0 = fmaf(a.y,  w1r[1], h0); h0 = fmaf(a.z,  w1r[2], h0);
            h0 = fmaf(b.x,  w1r[3], h0); h0 = fmaf(b.y,  w1r[4], h0); h0 = fmaf(b.z,  w1r[5], h0);
            h0 = fmaf(c1.x, w1r[6], h0); h0 = fmaf(c1.y, w1r[7], h0); h0 = fmaf(c1.z, w1r[8], h0);
            p1u[12 * 32 + lane] = pkdup(fmaxf(h0, 0.0f));
        }
        __syncwarp();

        // ---------- conv2 (lane -> out channels {lane, lane+32}), packed f32x2 ----------
        // Split into two position chunks to cap live registers at 72/thread.
        const ull b2pair = ((const ull*)(sm + B2P_OFF))[lane];
        float fa[6], fb[6];

        {   // chunk A: output positions 0..5 -> pool slots 0..2
            ull acc[6];
            #pragma unroll
            for (int j = 0; j < 6; ++j) acc[j] = b2pair;
            #pragma unroll 1
            for (int ci = 0; ci < 32; ++ci) {
                const ull* pp = p1u + ci;               // broadcast reads
                ull w0  = w2u[(ci     ) * 32 + lane];   // k=0
                ull w1v = w2u[(ci + 32) * 32 + lane];   // k=1
                ull w2v = w2u[(ci + 64) * 32 + lane];   // k=2
                ull q0 = pp[0],   q1 = pp[32],  q2 = pp[64],  q3 = pp[96];
                ull q4 = pp[128], q5 = pp[160], q6 = pp[192], q7 = pp[224];
                acc[0] = ffma2(q2, w2v, ffma2(q1, w1v, ffma2(q0, w0, acc[0])));
                acc[1] = ffma2(q3, w2v, ffma2(q2, w1v, ffma2(q1, w0, acc[1])));
                acc[2] = ffma2(q4, w2v, ffma2(q3, w1v, ffma2(q2, w0, acc[2])));
                acc[3] = ffma2(q5, w2v, ffma2(q4, w1v, ffma2(q3, w0, acc[3])));
                acc[4] = ffma2(q6, w2v, ffma2(q5, w1v, ffma2(q4, w0, acc[4])));
                acc[5] = ffma2(q7, w2v, ffma2(q6, w1v, ffma2(q5, w0, acc[5])));
            }
            #pragma unroll
            for (int jj = 0; jj < 3; ++jj) {
                float l0, h0c, l1, h1c;
                unpk(acc[2 * jj],     l0, h0c);
                unpk(acc[2 * jj + 1], l1, h1c);
                fa[jj] = fmaxf(fmaxf(l0, 0.f), fmaxf(l1, 0.f));
                fb[jj] = fmaxf(fmaxf(h0c, 0.f), fmaxf(h1c, 0.f));
            }
        }
        {   // chunk B: output positions 6..10 -> pool slots 3..5
            ull acc[5];
            #pragma unroll
            for (int j = 0; j < 5; ++j) acc[j] = b2pair;
            #pragma unroll 1
            for (int ci = 0; ci < 32; ++ci) {
                const ull* pp = p1u + ci;
                ull w0  = w2u[(ci     ) * 32 + lane];
                ull w1v = w2u[(ci + 32) * 32 + lane];
                ull w2v = w2u[(ci + 64) * 32 + lane];
                ull q6 = pp[192], q7 = pp[224], q8 = pp[256], q9 = pp[288];
                ull q10 = pp[320], q11 = pp[352], q12 = pp[384];
                acc[0] = ffma2(q8,  w2v, ffma2(q7,  w1v, ffma2(q6,  w0, acc[0])));
                acc[1] = ffma2(q9,  w2v, ffma2(q8,  w1v, ffma2(q7,  w0, acc[1])));
                acc[2] = ffma2(q10, w2v, ffma2(q9,  w1v, ffma2(q8,  w0, acc[2])));
                acc[3] = ffma2(q11, w2v, ffma2(q10, w1v, ffma2(q9,  w0, acc[3])));
                acc[4] = ffma2(q12, w2v, ffma2(q11, w1v, ffma2(q10, w0, acc[4])));
            }
            #pragma unroll
            for (int jj = 0; jj < 2; ++jj) {
                float l0, h0c, l1, h1c;
                unpk(acc[2 * jj],     l0, h0c);
                unpk(acc[2 * jj + 1], l1, h1c);
                fa[3 + jj] = fmaxf(fmaxf(l0, 0.f), fmaxf(l1, 0.f));
                fb[3 + jj] = fmaxf(fmaxf(h0c, 0.f), fmaxf(h1c, 0.f));
            }
            float l0, h0c;
            unpk(acc[4], l0, h0c);    // position 10, window of one
            fa[5] = fmaxf(l0, 0.f);
            fb[5] = fmaxf(h0c, 0.f);
        }

        // ---------- dense2 (packed over output pairs) + warp reduce + dense1 ----------
        ull fap[6], fbp[6];
        #pragma unroll
        for (int jj = 0; jj < 6; ++jj) { fap[jj] = pkdup(fa[jj]); fbp[jj] = pkdup(fb[jj]); }

        float d[10];
        #pragma unroll
        for (int q = 0; q < 5; ++q) {
            ull s = 0ull;   // packed {0.f, 0.f}
            const ull* wq = wdu + q * 384 + lane;
            #pragma unroll
            for (int jj = 0; jj < 6; ++jj) {
                s = ffma2(fap[jj], wq[jj * 64],      s);   // flat i = jj*64 + lane
                s = ffma2(fbp[jj], wq[jj * 64 + 32], s);   // flat i = jj*64 + 32 + lane
            }
            unpk(s, d[2 * q], d[2 * q + 1]);
        }
        #pragma unroll
        for (int off = 16; off > 0; off >>= 1) {
            #pragma unroll
            for (int o = 0; o < 10; ++o)
                d[o] += __shfl_xor_sync(0xffffffffu, d[o], off);
        }
        float y = sm[BD1_OFF];
        #pragma unroll
        for (int o = 0; o < 10; ++o)
            y = fmaf(fmaxf(d[o] + sm[BD2_OFF + o], 0.0f), sm[WD1_OFF + o], y);
        float accv = fmaf(10.0f, y, -6.0f);   // (MAXA-MINA)*y + MINA

        // ---------- recurrence + output ----------
        float pp2 = fmaf(0.1f, s24,  p24);
        float ps2 = fmaf(0.1f, accv, s24);
        if (lane == 0) out2[t] = make_float2(pp2, ps2);

        x0 = __shfl_down_sync(0xffffffffu, x0, 1);
        x1 = __shfl_down_sync(0xffffffffu, x1, 1);
        x2 = __shfl_down_sync(0xffffffffu, x2, 1);
        if (lane == 24) {
            x0 = (ldn.x - pp2) * (1.0f / 200.0f);
            x1 = ps2 * (1.0f / 40.0f);
            x2 = ldn.y * (1.0f / 40.0f);
        }
        p24 = pp2; s24 = ps2;
    }
}

extern "C" void kernel_launch(void* const* d_in, const int* in_sizes, int n_in,
                              void* d_out, int out_size)
{
    const float* lead = (const float*)d_in[0];   // (4096, 280, 2)
    const float* cur  = (const float*)d_in[1];   // (4096, 25, 2)
    // d_in[2] = mask (unused by the reference computation)
    const float* w1  = (const float*)d_in[3];
    const float* b1  = (const float*)d_in[4];
    const float* w2  = (const float*)d_in[5];
    const float* b2  = (const float*)d_in[6];
    const float* wd2 = (const float*)d_in[7];
    const float* bd2 = (const float*)d_in[8];
    const float* wd1 = (const float*)d_in[9];
    const float* bd1 = (const float*)d_in[10];
    float* out = (float*)d_out;                   // (4096, 256, 2)

    (void)in_sizes; (void)n_in; (void)out_size;

    size_t smem_bytes = (size_t)SMEM_FLOATS * sizeof(float);
    cudaFuncSetAttribute(rnncf_kernel,
                         cudaFuncAttributeMaxDynamicSharedMemorySize,
                         (int)smem_bytes);
    rnncf_kernel<<<NCTA, NTHREADS, smem_bytes>>>(
        lead, cur, w1, b1, w2, b2, wd2, bd2, wd1, bd1, out);
}